// round 14
// baseline (speedup 1.0000x reference)
#include <cuda_runtime.h>
#include <cuda_fp16.h>
#include <math.h>
#include <stdint.h>

#define Bc   2
#define Hc   32
#define Sc   1024
#define Dc   128
#define NBc  4
#define HIDc 4096
#define LOc  512
#define Mc   (Bc*Sc)

// ---------------- device scratch ---------------------------------------------
__device__ __half g_Xh[2][(size_t)Mc * HIDc];
__device__ __half g_Wah[2][(size_t)LOc * HIDc];
__device__ __half g_Wbh[2][(size_t)HIDc * LOc];
__device__ float  g_U32[4][(size_t)Mc * LOc];      // split-K partials (q0,q1,k0,k1)
__device__ __half g_Uh[2][(size_t)Mc * LOc];
__device__ __half g_Ph[2][(size_t)Bc * Hc * Sc * Dc];
__device__ float  g_w[(size_t)Bc * Hc * Sc * NBc];
__device__ int    g_blk[Bc * Sc];
__device__ int    g_tblk[Bc * 16];
__device__ float  g_cnt[Bc * Sc * NBc];

// ---------------- PTX helpers -------------------------------------------------
__device__ __forceinline__ uint32_t sptr(const void* p) {
    return (uint32_t)__cvta_generic_to_shared(p);
}
#define LDSM4(r, addr) asm volatile( \
    "ldmatrix.sync.aligned.m8n8.x4.shared.b16 {%0,%1,%2,%3}, [%4];" \
    : "=r"((r)[0]), "=r"((r)[1]), "=r"((r)[2]), "=r"((r)[3]) : "r"(addr))
#define MMA16816(c, a, b0, b1) asm volatile( \
    "mma.sync.aligned.m16n8k16.row.col.f32.f16.f16.f32 " \
    "{%0,%1,%2,%3},{%4,%5,%6,%7},{%8,%9},{%0,%1,%2,%3};" \
    : "+f"((c)[0]), "+f"((c)[1]), "+f"((c)[2]), "+f"((c)[3]) \
    : "r"((a)[0]), "r"((a)[1]), "r"((a)[2]), "r"((a)[3]), "r"(b0), "r"(b1))
#define CP16(dst, src) asm volatile( \
    "cp.async.cg.shared.global [%0], [%1], 16;" :: "r"(dst), "l"(src))
#define CPCOMMIT() asm volatile("cp.async.commit_group;")
#define CPWAIT1() asm volatile("cp.async.wait_group 1;")
#define CPWAIT2() asm volatile("cp.async.wait_group 2;")

// base-2 exp with 1/sqrt(D)*log2(e) prefolded; FMA-pipe only
__device__ __forceinline__ float fexp2s(float x) {
    const float CS = 0.08838834764831843f * 1.4426950408889634f;
    float t = fmaxf(x * CS, -110.f);
    float r = t + 12582912.f;
    int   i = __float_as_int(r) - 0x4B400000;
    float f = t - (r - 12582912.f);
    float p = 1.3333558e-3f;
    p = fmaf(p, f, 9.6181291e-3f);
    p = fmaf(p, f, 5.5504109e-2f);
    p = fmaf(p, f, 2.4022651e-1f);
    p = fmaf(p, f, 6.9314718e-1f);
    p = fmaf(p, f, 1.0f);
    return __int_as_float(__float_as_int(p) + (i << 23));
}

__device__ __forceinline__ void cvt4(float4 v, __half* dst) {
    *(__half2*)(dst)     = __floats2half2_rn(v.x, v.y);
    *(__half2*)(dst + 2) = __floats2half2_rn(v.z, v.w);
}

// ---------------- fused prep + input/weight conversion --------------------------
__global__ void prepconv_kernel(const float* __restrict__ query,
                                const float* __restrict__ key,
                                const float* __restrict__ wqa, const float* __restrict__ wka,
                                const float* __restrict__ wqb, const float* __restrict__ wkb,
                                const float* __restrict__ bmask) {
    int bid = blockIdx.x;
    if (bid < 2) {
        int b = bid;
        __shared__ int sblk[Sc];
        for (int k = threadIdx.x; k < Sc; k += blockDim.x) {
            int n = 0;
            for (int j = NBc - 1; j >= 0; --j)
                if (bmask[(b * NBc + j) * Sc + k] > 0.5f) n = j;
            sblk[k] = n;
            g_blk[b * Sc + k] = n;
        }
        __syncthreads();
        for (int q = threadIdx.x; q < Sc; q += blockDim.x) {
            int c0 = 0, c1 = 0, c2 = 0, c3 = 0;
            for (int k = 0; k <= q; ++k) {
                int n = sblk[k];
                c0 += (n == 0); c1 += (n == 1); c2 += (n == 2); c3 += (n == 3);
            }
            float* dst = &g_cnt[(b * Sc + q) * NBc];
            dst[0] = (float)c0; dst[1] = (float)c1; dst[2] = (float)c2; dst[3] = (float)c3;
        }
        if (threadIdx.x < 16) {
            int t = threadIdx.x;
            int u = sblk[t * 64];
            bool uni = true;
            for (int j = 1; j < 64; ++j) uni &= (sblk[t * 64 + j] == u);
            g_tblk[b * 16 + t] = uni ? u : -1;
        }
    } else if (bid < 2 + 16384) {
        int j = bid - 2;
        int z = j >> 13;
        int xb = j & 8191;
        const float* X = z ? key : query;
        __half* Hh = g_Xh[z];
        size_t i4 = (size_t)xb * blockDim.x + threadIdx.x;
        int m = (int)(i4 >> 10);
        int c = (int)(i4 & 1023) * 4;
        int h = c >> 7, d = c & 127, b = m >> 10, s = m & 1023;
        float4 v = *(const float4*)(X + (((size_t)(b * Hc + h)) * Sc + s) * Dc + d);
        cvt4(v, Hh + i4 * 4);
    } else {
        int j = bid - (2 + 16384);
        int sel = j >> 11;
        int xb = j & 2047;
        const float* src;
        __half* hi;
        switch (sel) {
            case 0:  src = wqa; hi = g_Wah[0]; break;
            case 1:  src = wka; hi = g_Wah[1]; break;
            case 2:  src = wqb; hi = g_Wbh[0]; break;
            default: src = wkb; hi = g_Wbh[1]; break;
        }
        size_t i4 = (size_t)xb * blockDim.x + threadIdx.x;
        float4 v = ((const float4*)src)[i4];
        cvt4(v, hi + i4 * 4);
    }
}

// combine split-K partials -> fp16 U
__global__ void ucomb_kernel() {
    int z = blockIdx.y;
    size_t i4 = (size_t)blockIdx.x * blockDim.x + threadIdx.x;
    float4 a = ((const float4*)g_U32[2 * z])[i4];
    float4 b = ((const float4*)g_U32[2 * z + 1])[i4];
    a.x += b.x; a.y += b.y; a.z += b.z; a.w += b.w;
    cvt4(a, g_Uh[z] + i4 * 4);
}

// ---------------- GEMM1: U32 partial = X * Wa^T (BN=128, splitK=2, 3-stage) ----
#define G1_S 3
__global__ __launch_bounds__(256, 3) void gemm1_tc() {
    extern __shared__ __half sm[];
    __half* Ah = sm;
    __half* Bh = Ah + G1_S * 128 * 40;

    int z = blockIdx.z;
    const __half* Xh = g_Xh[z >> 1];
    const __half* Wh = g_Wah[z >> 1];
    float* U = g_U32[z];
    int kbase = (z & 1) * (HIDc / 2);
    int n0 = blockIdx.x * 128;
    int m0 = blockIdx.y * 128;
    int tid = threadIdx.x;
    int lane = tid & 31, warp = tid >> 5;
    int wm = (warp & 3) * 32;
    int wn = (warp >> 2) * 64;

    float acc[2][8][4];
#pragma unroll
    for (int i = 0; i < 2; ++i)
#pragma unroll
        for (int j = 0; j < 8; ++j)
#pragma unroll
            for (int l = 0; l < 4; ++l) acc[i][j][l] = 0.f;

    auto load_stage = [&](int it, int s) {
        int kb = kbase + it * 32;
#pragma unroll
        for (int i = 0; i < 2; ++i) {
            int ch = tid + i * 256;
            int row = ch >> 2, c8 = (ch & 3) * 8;
            CP16(sptr(Ah + s * 128 * 40 + row * 40 + c8),
                 Xh + (size_t)(m0 + row) * HIDc + kb + c8);
            CP16(sptr(Bh + s * 128 * 40 + row * 40 + c8),
                 Wh + (size_t)(n0 + row) * HIDc + kb + c8);
        }
    };

    const int NIT = (HIDc / 2) / 32;     // 64
#pragma unroll
    for (int i = 0; i < G1_S - 1; ++i) {
        if (i < NIT) load_stage(i, i);
        CPCOMMIT();
    }

    for (int t = 0; t < NIT; ++t) {
        int slot = t % G1_S;
        CPWAIT1();
        __syncthreads();
        int lt = t + G1_S - 1;
        if (lt < NIT) load_stage(lt, lt % G1_S);
        CPCOMMIT();
        const __half* Ahs = Ah + slot * 128 * 40;
        const __half* Bhs = Bh + slot * 128 * 40;
#pragma unroll
        for (int ks = 0; ks < 2; ++ks) {
            uint32_t ah[2][4];
#pragma unroll
            for (int mf = 0; mf < 2; ++mf) {
                int r = wm + mf * 16 + (lane & 15);
                int c = ks * 16 + 8 * (lane >> 4);
                LDSM4(ah[mf], sptr(Ahs + r * 40 + c));
            }
            // one B-fragment group live at a time (4 regs) to fit reg budget
#pragma unroll
            for (int p = 0; p < 4; ++p) {
                uint32_t bh[4];
                int r = wn + p * 16 + (lane & 7) + ((lane & 16) >> 1);
                int c = ks * 16 + (lane & 8);
                LDSM4(bh, sptr(Bhs + r * 40 + c));
#pragma unroll
                for (int mf = 0; mf < 2; ++mf) {
                    MMA16816(acc[mf][2 * p],     ah[mf], bh[0], bh[1]);
                    MMA16816(acc[mf][2 * p + 1], ah[mf], bh[2], bh[3]);
                }
            }
        }
    }
#pragma unroll
    for (int mf = 0; mf < 2; ++mf)
#pragma unroll
        for (int nt = 0; nt < 8; ++nt) {
            int r = m0 + wm + mf * 16 + (lane >> 2);
            int c = n0 + wn + nt * 8 + (lane & 3) * 2;
            *(float2*)&U[(size_t)r * LOc + c]       = make_float2(acc[mf][nt][0], acc[mf][nt][1]);
            *(float2*)&U[(size_t)(r + 8) * LOc + c] = make_float2(acc[mf][nt][2], acc[mf][nt][3]);
        }
}

// ---------------- GEMM2: P(fp16) = U * Wb^T, scattered, 3-stage ----------------
#define G2_S 3
__global__ __launch_bounds__(256, 3) void gemm2_tc() {
    extern __shared__ __half sm[];
    __half* Ah = sm;
    __half* Bh = Ah + G2_S * 128 * 40;

    int z = blockIdx.z;
    const __half* Uh = g_Uh[z];
    const __half* Wh = g_Wbh[z];
    __half* P = g_Ph[z];
    int n0 = blockIdx.x * 128;
    int m0 = blockIdx.y * 128;
    int tid = threadIdx.x;
    int lane = tid & 31, warp = tid >> 5;
    int wm = (warp & 3) * 32;
    int wn = (warp >> 2) * 64;

    float acc[2][8][4];
#pragma unroll
    for (int i = 0; i < 2; ++i)
#pragma unroll
        for (int j = 0; j < 8; ++j)
#pragma unroll
            for (int l = 0; l < 4; ++l) acc[i][j][l] = 0.f;

    auto load_stage = [&](int it, int s) {
        int kb = it * 32;
#pragma unroll
        for (int i = 0; i < 2; ++i) {
            int ch = tid + i * 256;
            int row = ch >> 2, c8 = (ch & 3) * 8;
            CP16(sptr(Ah + s * 128 * 40 + row * 40 + c8),
                 Uh + (size_t)(m0 + row) * LOc + kb + c8);
            CP16(sptr(Bh + s * 128 * 40 + row * 40 + c8),
                 Wh + (size_t)(n0 + row) * LOc + kb + c8);
        }
    };

    const int NIT = LOc / 32;            // 16
#pragma unroll
    for (int i = 0; i < G2_S - 1; ++i) {
        if (i < NIT) load_stage(i, i);
        CPCOMMIT();
    }

    for (int t = 0; t < NIT; ++t) {
        int slot = t % G2_S;
        CPWAIT1();
        __syncthreads();
        int lt = t + G2_S - 1;
        if (lt < NIT) load_stage(lt, lt % G2_S);
        CPCOMMIT();
        const __half* Ahs = Ah + slot * 128 * 40;
        const __half* Bhs = Bh + slot * 128 * 40;
#pragma unroll
        for (int ks = 0; ks < 2; ++ks) {
            uint32_t ah[2][4];
#pragma unroll
            for (int mf = 0; mf < 2; ++mf) {
                int r = wm + mf * 16 + (lane & 15);
                int c = ks * 16 + 8 * (lane >> 4);
                LDSM4(ah[mf], sptr(Ahs + r * 40 + c));
            }
#pragma unroll
            for (int p = 0; p < 4; ++p) {
                uint32_t bh[4];
                int r = wn + p * 16 + (lane & 7) + ((lane & 16) >> 1);
                int c = ks * 16 + (lane & 8);
                LDSM4(bh, sptr(Bhs + r * 40 + c));
#pragma unroll
                for (int mf = 0; mf < 2; ++mf) {
                    MMA16816(acc[mf][2 * p],     ah[mf], bh[0], bh[1]);
                    MMA16816(acc[mf][2 * p + 1], ah[mf], bh[2], bh[3]);
                }
            }
        }
    }
#pragma unroll
    for (int mf = 0; mf < 2; ++mf)
#pragma unroll
        for (int nt = 0; nt < 8; ++nt) {
            int r = m0 + wm + mf * 16 + (lane >> 2);
            int c = n0 + wn + nt * 8 + (lane & 3) * 2;
            int h = c >> 7, d = c & 127;
            int bb = r >> 10, s2 = r & 1023;
            size_t base = (((size_t)(bb * Hc + h)) * Sc + s2) * Dc + d;
            *(__half2*)&P[base]          = __floats2half2_rn(acc[mf][nt][0], acc[mf][nt][1]);
            *(__half2*)&P[base + 8 * Dc] = __floats2half2_rn(acc[mf][nt][2], acc[mf][nt][3]);
        }
}

// ---------------- fused attention + block pooling (4-stage K pipeline) ---------
#define AT_S 4
__global__ __launch_bounds__(256) void attn_tc(const float* __restrict__ alpha_p) {
    extern __shared__ __half sm[];
    __half* Qs = sm;                 // [128][136]
    __half* Ks = Qs + 128 * 136;     // [AT_S][64][136]

    int qt = 7 - blockIdx.x;
    int bh = blockIdx.y;
    int b = bh >> 5;
    int q0 = qt * 128;
    int tid = threadIdx.x;
    int lane = tid & 31, warp = tid >> 5;

    const __half* Qp = g_Ph[0] + (size_t)bh * Sc * Dc;
    const __half* Kp = g_Ph[1] + (size_t)bh * Sc * Dc;

#pragma unroll
    for (int i = 0; i < 8; ++i) {
        int ch = tid + i * 256;
        int row = ch >> 4, c8 = (ch & 15) * 8;
        CP16(sptr(Qs + row * 136 + c8), Qp + (size_t)(q0 + row) * Dc + c8);
    }
    auto load_k = [&](int kt, int s) {
        int k0 = kt * 64;
#pragma unroll
        for (int i = 0; i < 4; ++i) {
            int ch = tid + i * 256;
            int row = ch >> 4, c8 = (ch & 15) * 8;
            CP16(sptr(Ks + s * 64 * 136 + row * 136 + c8), Kp + (size_t)(k0 + row) * Dc + c8);
        }
    };

    int NT = 2 * qt + 2;
#pragma unroll
    for (int i = 0; i < AT_S - 1; ++i) {
        if (i < NT) load_k(i, i);
        CPCOMMIT();
    }

    float ab[2][4];
#pragma unroll
    for (int i = 0; i < 2; ++i)
#pragma unroll
        for (int n = 0; n < 4; ++n) ab[i][n] = 0.f;

    int r0g = q0 + warp * 16 + (lane >> 2);

    for (int kt = 0; kt < NT; ++kt) {
        int slot = kt % AT_S;
        CPWAIT2();
        __syncthreads();
        int lt = kt + AT_S - 1;
        if (lt < NT) load_k(lt, lt % AT_S);
        CPCOMMIT();

        const __half* Kss = Ks + slot * 64 * 136;
        float acc[8][4];
#pragma unroll
        for (int j = 0; j < 8; ++j)
#pragma unroll
            for (int l = 0; l < 4; ++l) acc[j][l] = 0.f;

#pragma unroll
        for (int ks = 0; ks < 8; ++ks) {
            uint32_t a[4];
            {
                int r = warp * 16 + (lane & 15);
                int c = ks * 16 + 8 * (lane >> 4);
                LDSM4(a, sptr(Qs + r * 136 + c));
            }
            uint32_t bf[4][4];
#pragma unroll
            for (int p = 0; p < 4; ++p) {
                int r = p * 16 + (lane & 7) + ((lane & 16) >> 1);
                int c = ks * 16 + (lane & 8);
                LDSM4(bf[p], sptr(Kss + r * 136 + c));
            }
#pragma unroll
            for (int nt = 0; nt < 8; ++nt) {
                uint32_t* bp = &bf[nt >> 1][(nt & 1) * 2];
                MMA16816(acc[nt], a, bp[0], bp[1]);
            }
        }

        int k0 = kt * 64;
        int u = __ldg(&g_tblk[b * 16 + (k0 >> 6)]);
        bool needmask = (kt >= 2 * qt);
        float s0 = 0.f, s1 = 0.f;
#pragma unroll
        for (int nt = 0; nt < 8; ++nt) {
            int c0 = k0 + nt * 8 + (lane & 3) * 2;
            float e00 = fexp2s(acc[nt][0]);
            float e01 = fexp2s(acc[nt][1]);
            float e10 = fexp2s(acc[nt][2]);
            float e11 = fexp2s(acc[nt][3]);
            if (needmask) {
                if (c0 > r0g)         e00 = 0.f;
                if (c0 + 1 > r0g)     e01 = 0.f;
                if (c0 > r0g + 8)     e10 = 0.f;
                if (c0 + 1 > r0g + 8) e11 = 0.f;
            }
            if (u >= 0) {
                s0 += e00 + e01;
                s1 += e10 + e11;
            } else {
                int b0 = __ldg(&g_blk[b * Sc + c0]);
                int b1 = __ldg(&g_blk[b * Sc + c0 + 1]);
#pragma unroll
                for (int n = 0; n < 4; ++n) {
                    ab[0][n] += (b0 == n ? e00 : 0.f) + (b1 == n ? e01 : 0.f);
                    ab[1][n] += (b0 == n ? e10 : 0.f) + (b1 == n ? e11 : 0.f);
                }
            }
        }
        if (u >= 0) {
#pragma unroll
            for (int n = 0; n < 4; ++n) {
                ab[0][n] += (n == u) ? s0 : 0.f;
                ab[1][n] += (n == u) ? s1 : 0.f;
            }
        }
    }

#pragma unroll
    for (int off = 1; off <= 2; off <<= 1)
#pragma unroll
        for (int i = 0; i < 2; ++i)
#pragma unroll
            for (int n = 0; n < 4; ++n)
                ab[i][n] += __shfl_xor_sync(0xffffffffu, ab[i][n], off, 32);

    if ((lane & 3) == 0) {
        float alpha = *alpha_p;
#pragma unroll
        for (int i = 0; i < 2; ++i) {
            int r = r0g + i * 8;
            float Z = ab[i][0] + ab[i][1] + ab[i][2] + ab[i][3];
            float inv = alpha / Z;
            const float* cnt = &g_cnt[(b * Sc + r) * NBc];
            float* dst = &g_w[((size_t)bh * Sc + r) * NBc];
#pragma unroll
            for (int n = 0; n < NBc; ++n)
                dst[n] = ab[i][n] * inv / fmaxf(cnt[n], 1.f);
        }
    }
}

// ---------------- expand (standalone, high-occupancy, bandwidth-bound) ---------
__global__ void expand_kernel(float* __restrict__ out) {
    int row = blockIdx.x;
    int q = row & (Sc - 1);
    int bh = row >> 10;
    int b = bh >> 5;
    float4 w4 = __ldg((const float4*)&g_w[(size_t)row * NBc]);
    int k = threadIdx.x * 4;
    int4 bl = *(const int4*)&g_blk[b * Sc + k];
    float4 o;
    o.x = (k + 0 <= q) ? (bl.x == 0 ? w4.x : bl.x == 1 ? w4.y : bl.x == 2 ? w4.z : w4.w) : 0.f;
    o.y = (k + 1 <= q) ? (bl.y == 0 ? w4.x : bl.y == 1 ? w4.y : bl.y == 2 ? w4.z : w4.w) : 0.f;
    o.z = (k + 2 <= q) ? (bl.z == 0 ? w4.x : bl.z == 1 ? w4.y : bl.z == 2 ? w4.z : w4.w) : 0.f;
    o.w = (k + 3 <= q) ? (bl.w == 0 ? w4.x : bl.w == 1 ? w4.y : bl.w == 2 ? w4.z : w4.w) : 0.f;
    *(float4*)(out + (size_t)row * Sc + k) = o;
}

// ---------------- launch --------------------------------------------------------
extern "C" void kernel_launch(void* const* d_in, const int* in_sizes, int n_in,
                              void* d_out, int out_size) {
    const float* query = (const float*)d_in[0];
    const float* key   = (const float*)d_in[1];
    const float* Wqa   = (const float*)d_in[2];
    const float* Wqb   = (const float*)d_in[3];
    const float* Wka   = (const float*)d_in[4];
    const float* Wkb   = (const float*)d_in[5];
    const float* alpha = (const float*)d_in[6];
    const float* bmask = (const float*)d_in[7];
    float* out = (float*)d_out;

    const int SM_G1 = (G1_S * 128 * 40 * 2) * 2;                // 61440 B
    const int SM_G2 = (G2_S * 128 * 40 * 2) * 2;                // 61440 B
    const int SM_AT = (128 * 136 + AT_S * 64 * 136) * 2;        // 104448 B
    cudaFuncSetAttribute(gemm1_tc, cudaFuncAttributeMaxDynamicSharedMemorySize, SM_G1);
    cudaFuncSetAttribute(gemm2_tc, cudaFuncAttributeMaxDynamicSharedMemorySize, SM_G2);
    cudaFuncSetAttribute(attn_tc,  cudaFuncAttributeMaxDynamicSharedMemorySize, SM_AT);

    prepconv_kernel<<<2 + 16384 + 8192, 256>>>(query, key, Wqa, Wka, Wqb, Wkb, bmask);
    gemm1_tc<<<dim3(LOc / 128, Mc / 128, 4), 256, SM_G1>>>();
    ucomb_kernel<<<dim3(1024, 2), 256>>>();
    gemm2_tc<<<dim3(HIDc / 128, Mc / 128, 2), 256, SM_G2>>>();
    attn_tc<<<dim3(8, Bc * Hc), 256, SM_AT>>>(alpha);
    expand_kernel<<<Bc * Hc * Sc, 256>>>(out);
}

// round 15
// speedup vs baseline: 1.2093x; 1.2093x over previous
#include <cuda_runtime.h>
#include <cuda_fp16.h>
#include <math.h>
#include <stdint.h>

#define Bc   2
#define Hc   32
#define Sc   1024
#define Dc   128
#define NBc  4
#define HIDc 4096
#define LOc  512
#define Mc   (Bc*Sc)

// ---------------- device scratch ---------------------------------------------
__device__ __half g_Xh[2][(size_t)Mc * HIDc];
__device__ __half g_Wah[2][(size_t)LOc * HIDc];
__device__ __half g_Wbh[2][(size_t)HIDc * LOc];
__device__ float  g_U32[4][(size_t)Mc * LOc];      // split-K partials (q0,q1,k0,k1)
__device__ __half g_Uh[2][(size_t)Mc * LOc];
__device__ __half g_Ph[2][(size_t)Bc * Hc * Sc * Dc];
__device__ float  g_w[(size_t)Bc * Hc * Sc * NBc];
__device__ int    g_blk[Bc * Sc];
__device__ int    g_tblk[Bc * 16];
__device__ float  g_cnt[Bc * Sc * NBc];

// ---------------- PTX helpers -------------------------------------------------
__device__ __forceinline__ uint32_t sptr(const void* p) {
    return (uint32_t)__cvta_generic_to_shared(p);
}
#define LDSM4(r, addr) asm volatile( \
    "ldmatrix.sync.aligned.m8n8.x4.shared.b16 {%0,%1,%2,%3}, [%4];" \
    : "=r"((r)[0]), "=r"((r)[1]), "=r"((r)[2]), "=r"((r)[3]) : "r"(addr))
#define MMA16816(c, a, b0, b1) asm volatile( \
    "mma.sync.aligned.m16n8k16.row.col.f32.f16.f16.f32 " \
    "{%0,%1,%2,%3},{%4,%5,%6,%7},{%8,%9},{%0,%1,%2,%3};" \
    : "+f"((c)[0]), "+f"((c)[1]), "+f"((c)[2]), "+f"((c)[3]) \
    : "r"((a)[0]), "r"((a)[1]), "r"((a)[2]), "r"((a)[3]), "r"(b0), "r"(b1))
#define CP16(dst, src) asm volatile( \
    "cp.async.cg.shared.global [%0], [%1], 16;" :: "r"(dst), "l"(src))
#define CPCOMMIT() asm volatile("cp.async.commit_group;")
#define CPWAIT1() asm volatile("cp.async.wait_group 1;")
#define CPWAIT2() asm volatile("cp.async.wait_group 2;")
#define STCS4(addr, v) asm volatile( \
    "st.global.cs.v4.f32 [%0], {%1,%2,%3,%4};" \
    :: "l"(addr), "f"((v).x), "f"((v).y), "f"((v).z), "f"((v).w) : "memory")

// base-2 exp with 1/sqrt(D)*log2(e) prefolded; FMA-pipe only
__device__ __forceinline__ float fexp2s(float x) {
    const float CS = 0.08838834764831843f * 1.4426950408889634f;
    float t = fmaxf(x * CS, -110.f);
    float r = t + 12582912.f;
    int   i = __float_as_int(r) - 0x4B400000;
    float f = t - (r - 12582912.f);
    float p = 1.3333558e-3f;
    p = fmaf(p, f, 9.6181291e-3f);
    p = fmaf(p, f, 5.5504109e-2f);
    p = fmaf(p, f, 2.4022651e-1f);
    p = fmaf(p, f, 6.9314718e-1f);
    p = fmaf(p, f, 1.0f);
    return __int_as_float(__float_as_int(p) + (i << 23));
}

__device__ __forceinline__ void cvt4(float4 v, __half* dst) {
    *(__half2*)(dst)     = __floats2half2_rn(v.x, v.y);
    *(__half2*)(dst + 2) = __floats2half2_rn(v.z, v.w);
}

// ---------------- fused prep + input/weight conversion --------------------------
__global__ void prepconv_kernel(const float* __restrict__ query,
                                const float* __restrict__ key,
                                const float* __restrict__ wqa, const float* __restrict__ wka,
                                const float* __restrict__ wqb, const float* __restrict__ wkb,
                                const float* __restrict__ bmask) {
    int bid = blockIdx.x;
    if (bid < 2) {
        int b = bid;
        __shared__ int sblk[Sc];
        for (int k = threadIdx.x; k < Sc; k += blockDim.x) {
            int n = 0;
            for (int j = NBc - 1; j >= 0; --j)
                if (bmask[(b * NBc + j) * Sc + k] > 0.5f) n = j;
            sblk[k] = n;
            g_blk[b * Sc + k] = n;
        }
        __syncthreads();
        for (int q = threadIdx.x; q < Sc; q += blockDim.x) {
            int c0 = 0, c1 = 0, c2 = 0, c3 = 0;
            for (int k = 0; k <= q; ++k) {
                int n = sblk[k];
                c0 += (n == 0); c1 += (n == 1); c2 += (n == 2); c3 += (n == 3);
            }
            float* dst = &g_cnt[(b * Sc + q) * NBc];
            dst[0] = (float)c0; dst[1] = (float)c1; dst[2] = (float)c2; dst[3] = (float)c3;
        }
        if (threadIdx.x < 16) {
            int t = threadIdx.x;
            int u = sblk[t * 64];
            bool uni = true;
            for (int j = 1; j < 64; ++j) uni &= (sblk[t * 64 + j] == u);
            g_tblk[b * 16 + t] = uni ? u : -1;
        }
    } else if (bid < 2 + 16384) {
        int j = bid - 2;
        int z = j >> 13;
        int xb = j & 8191;
        const float* X = z ? key : query;
        __half* Hh = g_Xh[z];
        size_t i4 = (size_t)xb * blockDim.x + threadIdx.x;
        int m = (int)(i4 >> 10);
        int c = (int)(i4 & 1023) * 4;
        int h = c >> 7, d = c & 127, b = m >> 10, s = m & 1023;
        float4 v = *(const float4*)(X + (((size_t)(b * Hc + h)) * Sc + s) * Dc + d);
        cvt4(v, Hh + i4 * 4);
    } else {
        int j = bid - (2 + 16384);
        int sel = j >> 11;
        int xb = j & 2047;
        const float* src;
        __half* hi;
        switch (sel) {
            case 0:  src = wqa; hi = g_Wah[0]; break;
            case 1:  src = wka; hi = g_Wah[1]; break;
            case 2:  src = wqb; hi = g_Wbh[0]; break;
            default: src = wkb; hi = g_Wbh[1]; break;
        }
        size_t i4 = (size_t)xb * blockDim.x + threadIdx.x;
        float4 v = ((const float4*)src)[i4];
        cvt4(v, hi + i4 * 4);
    }
}

// combine split-K partials -> fp16 U
__global__ void ucomb_kernel() {
    int z = blockIdx.y;
    size_t i4 = (size_t)blockIdx.x * blockDim.x + threadIdx.x;
    float4 a = ((const float4*)g_U32[2 * z])[i4];
    float4 b = ((const float4*)g_U32[2 * z + 1])[i4];
    a.x += b.x; a.y += b.y; a.z += b.z; a.w += b.w;
    cvt4(a, g_Uh[z] + i4 * 4);
}

// ---------------- GEMM1: U32 partial = X * Wa^T (BN=128, splitK=2, 4-stage) ----
#define G1_S 4
__global__ __launch_bounds__(256) void gemm1_tc() {
    extern __shared__ __half sm[];
    __half* Ah = sm;
    __half* Bh = Ah + G1_S * 128 * 40;

    int z = blockIdx.z;
    const __half* Xh = g_Xh[z >> 1];
    const __half* Wh = g_Wah[z >> 1];
    float* U = g_U32[z];
    int kbase = (z & 1) * (HIDc / 2);
    int n0 = blockIdx.x * 128;
    int m0 = blockIdx.y * 128;
    int tid = threadIdx.x;
    int lane = tid & 31, warp = tid >> 5;
    int wm = (warp & 3) * 32;
    int wn = (warp >> 2) * 64;

    float acc[2][8][4];
#pragma unroll
    for (int i = 0; i < 2; ++i)
#pragma unroll
        for (int j = 0; j < 8; ++j)
#pragma unroll
            for (int l = 0; l < 4; ++l) acc[i][j][l] = 0.f;

    auto load_stage = [&](int it, int s) {
        int kb = kbase + it * 32;
#pragma unroll
        for (int i = 0; i < 2; ++i) {
            int ch = tid + i * 256;
            int row = ch >> 2, c8 = (ch & 3) * 8;
            CP16(sptr(Ah + s * 128 * 40 + row * 40 + c8),
                 Xh + (size_t)(m0 + row) * HIDc + kb + c8);
            CP16(sptr(Bh + s * 128 * 40 + row * 40 + c8),
                 Wh + (size_t)(n0 + row) * HIDc + kb + c8);
        }
    };

    const int NIT = (HIDc / 2) / 32;     // 64
#pragma unroll
    for (int i = 0; i < G1_S - 1; ++i) {
        if (i < NIT) load_stage(i, i);
        CPCOMMIT();
    }

    for (int t = 0; t < NIT; ++t) {
        int slot = t % G1_S;
        CPWAIT2();
        __syncthreads();
        int lt = t + G1_S - 1;
        if (lt < NIT) load_stage(lt, lt % G1_S);
        CPCOMMIT();
        const __half* Ahs = Ah + slot * 128 * 40;
        const __half* Bhs = Bh + slot * 128 * 40;
#pragma unroll
        for (int ks = 0; ks < 2; ++ks) {
            uint32_t ah[2][4];
#pragma unroll
            for (int mf = 0; mf < 2; ++mf) {
                int r = wm + mf * 16 + (lane & 15);
                int c = ks * 16 + 8 * (lane >> 4);
                LDSM4(ah[mf], sptr(Ahs + r * 40 + c));
            }
            uint32_t bh[4][4];
#pragma unroll
            for (int p = 0; p < 4; ++p) {
                int r = wn + p * 16 + (lane & 7) + ((lane & 16) >> 1);
                int c = ks * 16 + (lane & 8);
                LDSM4(bh[p], sptr(Bhs + r * 40 + c));
            }
#pragma unroll
            for (int mf = 0; mf < 2; ++mf)
#pragma unroll
                for (int nt = 0; nt < 8; ++nt) {
                    uint32_t* bp = &bh[nt >> 1][(nt & 1) * 2];
                    MMA16816(acc[mf][nt], ah[mf], bp[0], bp[1]);
                }
        }
    }
#pragma unroll
    for (int mf = 0; mf < 2; ++mf)
#pragma unroll
        for (int nt = 0; nt < 8; ++nt) {
            int r = m0 + wm + mf * 16 + (lane >> 2);
            int c = n0 + wn + nt * 8 + (lane & 3) * 2;
            *(float2*)&U[(size_t)r * LOc + c]       = make_float2(acc[mf][nt][0], acc[mf][nt][1]);
            *(float2*)&U[(size_t)(r + 8) * LOc + c] = make_float2(acc[mf][nt][2], acc[mf][nt][3]);
        }
}

// ---------------- GEMM2: P(fp16) = U * Wb^T, scattered, 3-stage ----------------
#define G2_S 3
__global__ __launch_bounds__(256) void gemm2_tc() {
    extern __shared__ __half sm[];
    __half* Ah = sm;
    __half* Bh = Ah + G2_S * 128 * 40;

    int z = blockIdx.z;
    const __half* Uh = g_Uh[z];
    const __half* Wh = g_Wbh[z];
    __half* P = g_Ph[z];
    int n0 = blockIdx.x * 128;
    int m0 = blockIdx.y * 128;
    int tid = threadIdx.x;
    int lane = tid & 31, warp = tid >> 5;
    int wm = (warp & 3) * 32;
    int wn = (warp >> 2) * 64;

    float acc[2][8][4];
#pragma unroll
    for (int i = 0; i < 2; ++i)
#pragma unroll
        for (int j = 0; j < 8; ++j)
#pragma unroll
            for (int l = 0; l < 4; ++l) acc[i][j][l] = 0.f;

    auto load_stage = [&](int it, int s) {
        int kb = it * 32;
#pragma unroll
        for (int i = 0; i < 2; ++i) {
            int ch = tid + i * 256;
            int row = ch >> 2, c8 = (ch & 3) * 8;
            CP16(sptr(Ah + s * 128 * 40 + row * 40 + c8),
                 Uh + (size_t)(m0 + row) * LOc + kb + c8);
            CP16(sptr(Bh + s * 128 * 40 + row * 40 + c8),
                 Wh + (size_t)(n0 + row) * LOc + kb + c8);
        }
    };

    const int NIT = LOc / 32;            // 16
#pragma unroll
    for (int i = 0; i < G2_S - 1; ++i) {
        if (i < NIT) load_stage(i, i);
        CPCOMMIT();
    }

    for (int t = 0; t < NIT; ++t) {
        int slot = t % G2_S;
        CPWAIT1();
        __syncthreads();
        int lt = t + G2_S - 1;
        if (lt < NIT) load_stage(lt, lt % G2_S);
        CPCOMMIT();
        const __half* Ahs = Ah + slot * 128 * 40;
        const __half* Bhs = Bh + slot * 128 * 40;
#pragma unroll
        for (int ks = 0; ks < 2; ++ks) {
            uint32_t ah[2][4];
#pragma unroll
            for (int mf = 0; mf < 2; ++mf) {
                int r = wm + mf * 16 + (lane & 15);
                int c = ks * 16 + 8 * (lane >> 4);
                LDSM4(ah[mf], sptr(Ahs + r * 40 + c));
            }
            uint32_t bh[4][4];
#pragma unroll
            for (int p = 0; p < 4; ++p) {
                int r = wn + p * 16 + (lane & 7) + ((lane & 16) >> 1);
                int c = ks * 16 + (lane & 8);
                LDSM4(bh[p], sptr(Bhs + r * 40 + c));
            }
#pragma unroll
            for (int mf = 0; mf < 2; ++mf)
#pragma unroll
                for (int nt = 0; nt < 8; ++nt) {
                    uint32_t* bp = &bh[nt >> 1][(nt & 1) * 2];
                    MMA16816(acc[mf][nt], ah[mf], bp[0], bp[1]);
                }
        }
    }
#pragma unroll
    for (int mf = 0; mf < 2; ++mf)
#pragma unroll
        for (int nt = 0; nt < 8; ++nt) {
            int r = m0 + wm + mf * 16 + (lane >> 2);
            int c = n0 + wn + nt * 8 + (lane & 3) * 2;
            int h = c >> 7, d = c & 127;
            int bb = r >> 10, s2 = r & 1023;
            size_t base = (((size_t)(bb * Hc + h)) * Sc + s2) * Dc + d;
            *(__half2*)&P[base]          = __floats2half2_rn(acc[mf][nt][0], acc[mf][nt][1]);
            *(__half2*)&P[base + 8 * Dc] = __floats2half2_rn(acc[mf][nt][2], acc[mf][nt][3]);
        }
}

// ---------------- fused attention + block pooling (4-stage K pipeline) ---------
#define AT_S 4
__global__ __launch_bounds__(256) void attn_tc(const float* __restrict__ alpha_p) {
    extern __shared__ __half sm[];
    __half* Qs = sm;                 // [128][136]
    __half* Ks = Qs + 128 * 136;     // [AT_S][64][136]

    int qt = 7 - blockIdx.x;
    int bh = blockIdx.y;
    int b = bh >> 5;
    int q0 = qt * 128;
    int tid = threadIdx.x;
    int lane = tid & 31, warp = tid >> 5;

    const __half* Qp = g_Ph[0] + (size_t)bh * Sc * Dc;
    const __half* Kp = g_Ph[1] + (size_t)bh * Sc * Dc;

#pragma unroll
    for (int i = 0; i < 8; ++i) {
        int ch = tid + i * 256;
        int row = ch >> 4, c8 = (ch & 15) * 8;
        CP16(sptr(Qs + row * 136 + c8), Qp + (size_t)(q0 + row) * Dc + c8);
    }
    auto load_k = [&](int kt, int s) {
        int k0 = kt * 64;
#pragma unroll
        for (int i = 0; i < 4; ++i) {
            int ch = tid + i * 256;
            int row = ch >> 4, c8 = (ch & 15) * 8;
            CP16(sptr(Ks + s * 64 * 136 + row * 136 + c8), Kp + (size_t)(k0 + row) * Dc + c8);
        }
    };

    int NT = 2 * qt + 2;
#pragma unroll
    for (int i = 0; i < AT_S - 1; ++i) {
        if (i < NT) load_k(i, i);
        CPCOMMIT();
    }

    float ab[2][4];
#pragma unroll
    for (int i = 0; i < 2; ++i)
#pragma unroll
        for (int n = 0; n < 4; ++n) ab[i][n] = 0.f;

    int r0g = q0 + warp * 16 + (lane >> 2);

    for (int kt = 0; kt < NT; ++kt) {
        int slot = kt % AT_S;
        CPWAIT2();
        __syncthreads();
        int lt = kt + AT_S - 1;
        if (lt < NT) load_k(lt, lt % AT_S);
        CPCOMMIT();

        const __half* Kss = Ks + slot * 64 * 136;
        float acc[8][4];
#pragma unroll
        for (int j = 0; j < 8; ++j)
#pragma unroll
            for (int l = 0; l < 4; ++l) acc[j][l] = 0.f;

#pragma unroll
        for (int ks = 0; ks < 8; ++ks) {
            uint32_t a[4];
            {
                int r = warp * 16 + (lane & 15);
                int c = ks * 16 + 8 * (lane >> 4);
                LDSM4(a, sptr(Qs + r * 136 + c));
            }
            uint32_t bf[4][4];
#pragma unroll
            for (int p = 0; p < 4; ++p) {
                int r = p * 16 + (lane & 7) + ((lane & 16) >> 1);
                int c = ks * 16 + (lane & 8);
                LDSM4(bf[p], sptr(Kss + r * 136 + c));
            }
#pragma unroll
            for (int nt = 0; nt < 8; ++nt) {
                uint32_t* bp = &bf[nt >> 1][(nt & 1) * 2];
                MMA16816(acc[nt], a, bp[0], bp[1]);
            }
        }

        int k0 = kt * 64;
        int u = __ldg(&g_tblk[b * 16 + (k0 >> 6)]);
        bool needmask = (kt >= 2 * qt);
        float s0 = 0.f, s1 = 0.f;
#pragma unroll
        for (int nt = 0; nt < 8; ++nt) {
            int c0 = k0 + nt * 8 + (lane & 3) * 2;
            float e00 = fexp2s(acc[nt][0]);
            float e01 = fexp2s(acc[nt][1]);
            float e10 = fexp2s(acc[nt][2]);
            float e11 = fexp2s(acc[nt][3]);
            if (needmask) {
                if (c0 > r0g)         e00 = 0.f;
                if (c0 + 1 > r0g)     e01 = 0.f;
                if (c0 > r0g + 8)     e10 = 0.f;
                if (c0 + 1 > r0g + 8) e11 = 0.f;
            }
            if (u >= 0) {
                s0 += e00 + e01;
                s1 += e10 + e11;
            } else {
                int b0 = __ldg(&g_blk[b * Sc + c0]);
                int b1 = __ldg(&g_blk[b * Sc + c0 + 1]);
#pragma unroll
                for (int n = 0; n < 4; ++n) {
                    ab[0][n] += (b0 == n ? e00 : 0.f) + (b1 == n ? e01 : 0.f);
                    ab[1][n] += (b0 == n ? e10 : 0.f) + (b1 == n ? e11 : 0.f);
                }
            }
        }
        if (u >= 0) {
#pragma unroll
            for (int n = 0; n < 4; ++n) {
                ab[0][n] += (n == u) ? s0 : 0.f;
                ab[1][n] += (n == u) ? s1 : 0.f;
            }
        }
    }

#pragma unroll
    for (int off = 1; off <= 2; off <<= 1)
#pragma unroll
        for (int i = 0; i < 2; ++i)
#pragma unroll
            for (int n = 0; n < 4; ++n)
                ab[i][n] += __shfl_xor_sync(0xffffffffu, ab[i][n], off, 32);

    if ((lane & 3) == 0) {
        float alpha = *alpha_p;
#pragma unroll
        for (int i = 0; i < 2; ++i) {
            int r = r0g + i * 8;
            float Z = ab[i][0] + ab[i][1] + ab[i][2] + ab[i][3];
            float inv = alpha / Z;
            const float* cnt = &g_cnt[(b * Sc + r) * NBc];
            float* dst = &g_w[((size_t)bh * Sc + r) * NBc];
#pragma unroll
            for (int n = 0; n < NBc; ++n)
                dst[n] = ab[i][n] * inv / fmaxf(cnt[n], 1.f);
        }
    }
}

// ---------------- expand (standalone, streaming stores) -------------------------
__global__ void expand_kernel(float* __restrict__ out) {
    int row = blockIdx.x;
    int q = row & (Sc - 1);
    int bh = row >> 10;
    int b = bh >> 5;
    float4 w4 = __ldg((const float4*)&g_w[(size_t)row * NBc]);
    int k = threadIdx.x * 4;
    int4 bl = *(const int4*)&g_blk[b * Sc + k];
    float4 o;
    o.x = (k + 0 <= q) ? (bl.x == 0 ? w4.x : bl.x == 1 ? w4.y : bl.x == 2 ? w4.z : w4.w) : 0.f;
    o.y = (k + 1 <= q) ? (bl.y == 0 ? w4.x : bl.y == 1 ? w4.y : bl.y == 2 ? w4.z : w4.w) : 0.f;
    o.z = (k + 2 <= q) ? (bl.z == 0 ? w4.x : bl.z == 1 ? w4.y : bl.z == 2 ? w4.z : w4.w) : 0.f;
    o.w = (k + 3 <= q) ? (bl.w == 0 ? w4.x : bl.w == 1 ? w4.y : bl.w == 2 ? w4.z : w4.w) : 0.f;
    STCS4(out + (size_t)row * Sc + k, o);
}

// ---------------- launch --------------------------------------------------------
extern "C" void kernel_launch(void* const* d_in, const int* in_sizes, int n_in,
                              void* d_out, int out_size) {
    const float* query = (const float*)d_in[0];
    const float* key   = (const float*)d_in[1];
    const float* Wqa   = (const float*)d_in[2];
    const float* Wqb   = (const float*)d_in[3];
    const float* Wka   = (const float*)d_in[4];
    const float* Wkb   = (const float*)d_in[5];
    const float* alpha = (const float*)d_in[6];
    const float* bmask = (const float*)d_in[7];
    float* out = (float*)d_out;

    const int SM_G1 = (G1_S * 128 * 40 * 2) * 2;                // 81920 B
    const int SM_G2 = (G2_S * 128 * 40 * 2) * 2;                // 61440 B
    const int SM_AT = (128 * 136 + AT_S * 64 * 136) * 2;        // 104448 B
    cudaFuncSetAttribute(gemm1_tc, cudaFuncAttributeMaxDynamicSharedMemorySize, SM_G1);
    cudaFuncSetAttribute(gemm2_tc, cudaFuncAttributeMaxDynamicSharedMemorySize, SM_G2);
    cudaFuncSetAttribute(attn_tc,  cudaFuncAttributeMaxDynamicSharedMemorySize, SM_AT);

    prepconv_kernel<<<2 + 16384 + 8192, 256>>>(query, key, Wqa, Wka, Wqb, Wkb, bmask);
    gemm1_tc<<<dim3(LOc / 128, Mc / 128, 4), 256, SM_G1>>>();
    ucomb_kernel<<<dim3(1024, 2), 256>>>();
    gemm2_tc<<<dim3(HIDc / 128, Mc / 128, 2), 256, SM_G2>>>();
    attn_tc<<<dim3(8, Bc * Hc), 256, SM_AT>>>(alpha);
    expand_kernel<<<Bc * Hc * Sc, 256>>>(out);
}